// round 3
// baseline (speedup 1.0000x reference)
#include <cuda_runtime.h>
#include <cstdint>

// LatticeSnake: B=32, L=512, W=9. Output [B, L, 9,9,9, 1] fp32 (48 MB).
// Doubled walk coords (the 2(L-1) grid offset cancels):
//   residue j:   p = 2*idx[j],         v = acids[j]*mask[j]
//   midpoint k:  p = idx[k]+idx[k+1],  v = (acids[k]+acids[k+1]+1)*mask[k+1]
//   window i:    rel = p - 2*idx[i]+4, hit iff all rel in [0,8]
//
// R3: two kernels.
//   A) zero-fill 48 MB with pure grid-stride STG.128 (write-throughput floor).
//   B) scatter: 32 windows/CTA, coords staged to smem (int4), hierarchical
//      bbox (group -> 4 sub-groups of 8), sparse hits via global RED.ADD.F32.

#define LS_L    512
#define LS_W    9
#define LS_W3   729
#define LS_R    32              // windows per scatter CTA
#define LS_NSUB 4               // sub-groups of 8 windows
#define LS_NT   256
#define LS_NG   (LS_L / LS_R)   // 16 groups per batch

// ---------------- Kernel A: zero-fill ----------------
__global__ __launch_bounds__(LS_NT)
void ls_fill_kernel(float4* __restrict__ out4, int n4)
{
    const float4 z = make_float4(0.f, 0.f, 0.f, 0.f);
    const int stride = gridDim.x * LS_NT;
    for (int i = blockIdx.x * LS_NT + threadIdx.x; i < n4; i += stride)
        out4[i] = z;
}

// ---------------- Kernel B: scatter ----------------
__global__ __launch_bounds__(LS_NT)
void ls_scatter_kernel(const float* __restrict__ acids,
                       const float* __restrict__ mask,
                       const int*   __restrict__ idx,
                       float*       __restrict__ out)
{
    __shared__ int sidx[LS_L * 3];   // this batch's coords, 6144 B

    const int b   = blockIdx.x >> 4;           // / LS_NG
    const int g   = blockIdx.x & (LS_NG - 1);
    const int i0  = g * LS_R;
    const int tid = threadIdx.x;

    const int*   gi = idx   + (size_t)b * LS_L * 3;
    const float* ga = acids + (size_t)b * LS_L;
    const float* gm = mask  + (size_t)b * LS_L;
    float* gout = out + (size_t)(b * LS_L + i0) * LS_W3;

    // stage coords: 1536 ints = 384 int4, coalesced
    {
        const int4* gi4 = reinterpret_cast<const int4*>(gi);
        int4* s4 = reinterpret_cast<int4*>(sidx);
        #pragma unroll
        for (int e = tid; e < (LS_L * 3) / 4; e += LS_NT) s4[e] = gi4[e];
    }
    __syncthreads();

    // sub-group bboxes (doubled coords, expanded by window radius 4)
    int sxl[LS_NSUB], sxh[LS_NSUB], syl[LS_NSUB], syh[LS_NSUB],
        szl[LS_NSUB], szh[LS_NSUB];
    int gxl =  0x7fffffff, gyl =  0x7fffffff, gzl =  0x7fffffff;
    int gxh = -0x7fffffff, gyh = -0x7fffffff, gzh = -0x7fffffff;
    #pragma unroll
    for (int s = 0; s < LS_NSUB; s++) {
        int xl =  0x7fffffff, yl =  0x7fffffff, zl =  0x7fffffff;
        int xh = -0x7fffffff, yh = -0x7fffffff, zh = -0x7fffffff;
        #pragma unroll
        for (int r = 0; r < 8; r++) {
            const int jj = 3 * (i0 + s * 8 + r);
            const int x = 2 * sidx[jj + 0];
            const int y = 2 * sidx[jj + 1];
            const int z = 2 * sidx[jj + 2];
            xl = min(xl, x); xh = max(xh, x);
            yl = min(yl, y); yh = max(yh, y);
            zl = min(zl, z); zh = max(zh, z);
        }
        sxl[s] = xl - 4; sxh[s] = xh + 4;
        syl[s] = yl - 4; syh[s] = yh + 4;
        szl[s] = zl - 4; szh[s] = zh + 4;
        gxl = min(gxl, sxl[s]); gxh = max(gxh, sxh[s]);
        gyl = min(gyl, syl[s]); gyh = max(gyh, syh[s]);
        gzl = min(gzl, szl[s]); gzh = max(gzh, szh[s]);
    }

    // all M = 1023 snake points
    const int M = 2 * LS_L - 1;
    #pragma unroll 4
    for (int j = tid; j < M; j += LS_NT) {
        int px, py, pz, k;
        bool is_mid;
        if (j < LS_L) {
            const int jj = 3 * j;
            px = 2 * sidx[jj + 0];
            py = 2 * sidx[jj + 1];
            pz = 2 * sidx[jj + 2];
            k = j; is_mid = false;
        } else {
            k = j - LS_L;                       // 0 .. L-2
            const int jj = 3 * k;
            px = sidx[jj + 0] + sidx[jj + 3];
            py = sidx[jj + 1] + sidx[jj + 4];
            pz = sidx[jj + 2] + sidx[jj + 5];
            is_mid = true;
        }

        if (px < gxl || px > gxh ||
            py < gyl || py > gyh ||
            pz < gzl || pz > gzh) continue;

        // lazy value load: only for points inside the group bbox
        float v;
        if (is_mid) v = (ga[k] + ga[k + 1] + 1.0f) * gm[k + 1];
        else        v = ga[k] * gm[k];

        #pragma unroll
        for (int s = 0; s < LS_NSUB; s++) {
            if (px < sxl[s] || px > sxh[s] ||
                py < syl[s] || py > syh[s] ||
                pz < szl[s] || pz > szh[s]) continue;
            #pragma unroll
            for (int r = 0; r < 8; r++) {
                const int w  = s * 8 + r;
                const int jj = 3 * (i0 + w);
                const unsigned rx = (unsigned)(px - 2 * sidx[jj + 0] + 4);
                const unsigned ry = (unsigned)(py - 2 * sidx[jj + 1] + 4);
                const unsigned rz = (unsigned)(pz - 2 * sidx[jj + 2] + 4);
                if (rx <= 8u && ry <= 8u && rz <= 8u) {
                    const int lin = (int)((rx * LS_W + ry) * LS_W + rz);
                    atomicAdd(&gout[w * LS_W3 + lin], v);   // RED.ADD.F32
                }
            }
        }
    }
}

extern "C" void kernel_launch(void* const* d_in, const int* in_sizes, int n_in,
                              void* d_out, int out_size)
{
    const float* acids = (const float*)d_in[0];   // [B, L]
    const float* mask  = (const float*)d_in[1];   // [B, L]
    const int*   idx   = (const int*)  d_in[2];   // [B, L, 3]
    float*       out   = (float*)d_out;           // [B, L, 9,9,9, 1]

    const int nB = in_sizes[0] / LS_L;            // 32
    const int n4 = (nB * LS_L * LS_W3) / 4;       // 2,985,984 float4 (exact)

    // A: zero-fill (pure write throughput)
    ls_fill_kernel<<<148 * 8, LS_NT>>>(reinterpret_cast<float4*>(out), n4);
    // B: sparse scatter (stream-ordered after A)
    ls_scatter_kernel<<<nB * LS_NG, LS_NT>>>(acids, mask, idx, out);
}

// round 4
// speedup vs baseline: 1.3221x; 1.3221x over previous
#include <cuda_runtime.h>
#include <cstdint>

// LatticeSnake: B=32, L=512, W=9. Output [B, L, 9,9,9, 1] fp32 (48 MB).
// Doubled walk coords (the 2(L-1) grid offset cancels):
//   residue j:   p = 2*idx[j],         v = acids[j]*mask[j]
//   midpoint k:  p = idx[k]+idx[k+1],  v = (acids[k]+acids[k+1]+1)*mask[k+1]
//   window i:    rel = p - 2*idx[i]+4, hit iff all rel in [0,8]
//
// R4: fused, 16 windows/CTA (CTA writes ONLY its own slice -> __syncthreads
// suffices for fill-before-RED ordering).
//   fill:    STG.128 zero own 45.6KB slice
//   phase A: dense scan of 1023 points, ballot-compact group-bbox survivors
//            into packed smem list (divergence-free downstream)
//   phase B: dense (survivor x window) pair loop, hits -> RED.ADD.F32

#define LS_L   512
#define LS_W   9
#define LS_W3  729
#define LS_R   16               // windows per CTA
#define LS_NT  256
#define LS_NG  (LS_L / LS_R)    // 32 groups per batch
#define LS_M   (2 * LS_L - 1)   // 1023 snake points

__global__ __launch_bounds__(LS_NT)
void lattice_snake_kernel(const float* __restrict__ acids,
                          const float* __restrict__ mask,
                          const int*   __restrict__ idx,
                          float*       __restrict__ out)
{
    __shared__ int4 surv[LS_M];        // packed survivors: px,py,pz,val_bits
    __shared__ int  sidx[LS_L * 3];    // batch coords
    __shared__ int4 scen[LS_R];        // window centers (doubled)
    __shared__ int  sCount;

    const int b   = blockIdx.x >> 5;            // / LS_NG
    const int g   = blockIdx.x & (LS_NG - 1);
    const int i0  = g * LS_R;
    const int tid = threadIdx.x;
    const int lane = tid & 31;

    const int*   gi = idx   + (size_t)b * LS_L * 3;
    const float* ga = acids + (size_t)b * LS_L;
    const float* gm = mask  + (size_t)b * LS_L;
    float* gout = out + (size_t)(b * LS_L + i0) * LS_W3;

    // ---- stage coords (384 int4, coalesced) ----
    {
        const int4* gi4 = reinterpret_cast<const int4*>(gi);
        int4* s4 = reinterpret_cast<int4*>(sidx);
        #pragma unroll
        for (int e = tid; e < (LS_L * 3) / 4; e += LS_NT) s4[e] = gi4[e];
    }
    if (tid == 0) sCount = 0;
    __syncthreads();

    // ---- window centers + group bbox (all threads compute bbox in regs) ----
    int gxl =  0x7fffffff, gyl =  0x7fffffff, gzl =  0x7fffffff;
    int gxh = -0x7fffffff, gyh = -0x7fffffff, gzh = -0x7fffffff;
    #pragma unroll
    for (int r = 0; r < LS_R; r++) {
        const int jj = 3 * (i0 + r);
        const int x = 2 * sidx[jj + 0];
        const int y = 2 * sidx[jj + 1];
        const int z = 2 * sidx[jj + 2];
        if (tid == r) scen[r] = make_int4(x, y, z, 0);
        gxl = min(gxl, x); gxh = max(gxh, x);
        gyl = min(gyl, y); gyh = max(gyh, y);
        gzl = min(gzl, z); gzh = max(gzh, z);
    }
    gxl -= 4; gxh += 4; gyl -= 4; gyh += 4; gzl -= 4; gzh += 4;

    // ---- fill: zero own slice (16*729 = 11664 floats = 2916 float4) ----
    {
        float4* o4 = reinterpret_cast<float4*>(gout);
        const float4 z = make_float4(0.f, 0.f, 0.f, 0.f);
        #pragma unroll
        for (int e = tid; e < (LS_R * LS_W3) / 4; e += LS_NT) o4[e] = z;
    }

    // ---- phase A: scan 1023 points, ballot-compact bbox survivors ----
    for (int j0 = 0; j0 < LS_M; j0 += LS_NT) {
        const int j = j0 + tid;
        int px = 0, py = 0, pz = 0, k = 0;
        bool isRes = false, hit = false;
        if (j < LS_M) {
            isRes = (j < LS_L);
            k = isRes ? j : j - LS_L;
            const int jj = 3 * k;
            if (isRes) {
                px = 2 * sidx[jj + 0];
                py = 2 * sidx[jj + 1];
                pz = 2 * sidx[jj + 2];
            } else {
                px = sidx[jj + 0] + sidx[jj + 3];
                py = sidx[jj + 1] + sidx[jj + 4];
                pz = sidx[jj + 2] + sidx[jj + 5];
            }
            hit = (px >= gxl) & (px <= gxh) &
                  (py >= gyl) & (py <= gyh) &
                  (pz >= gzl) & (pz <= gzh);
        }
        const unsigned m = __ballot_sync(0xffffffffu, hit);
        if (m == 0) continue;
        const int leader = __ffs(m) - 1;
        int base = 0;
        if (lane == leader) base = atomicAdd(&sCount, __popc(m));
        base = __shfl_sync(0xffffffffu, base, leader);
        if (hit) {
            const int pos = base + __popc(m & ((1u << lane) - 1u));
            const float v = isRes ? ga[k] * gm[k]
                                  : (ga[k] + ga[k + 1] + 1.0f) * gm[k + 1];
            surv[pos] = make_int4(px, py, pz, __float_as_int(v));
        }
    }
    __syncthreads();   // fill STGs + survivors + centers all visible/ordered

    // ---- phase B: dense (survivor x window) pairs -> RED hits ----
    const int nPairs = sCount * LS_R;
    for (int t = tid; t < nPairs; t += LS_NT) {
        const int s = t >> 4;          // survivor index
        const int w = t & (LS_R - 1);  // window index
        const int4 p = surv[s];
        const int4 c = scen[w];
        const unsigned rx = (unsigned)(p.x - c.x + 4);
        const unsigned ry = (unsigned)(p.y - c.y + 4);
        const unsigned rz = (unsigned)(p.z - c.z + 4);
        if (rx <= 8u && ry <= 8u && rz <= 8u) {
            const int lin = (int)((rx * LS_W + ry) * LS_W + rz);
            atomicAdd(&gout[w * LS_W3 + lin], __int_as_float(p.w));
        }
    }
}

extern "C" void kernel_launch(void* const* d_in, const int* in_sizes, int n_in,
                              void* d_out, int out_size)
{
    const float* acids = (const float*)d_in[0];   // [B, L]
    const float* mask  = (const float*)d_in[1];   // [B, L]
    const int*   idx   = (const int*)  d_in[2];   // [B, L, 3]
    float*       out   = (float*)d_out;           // [B, L, 9,9,9, 1]

    const int nB = in_sizes[0] / LS_L;            // 32
    lattice_snake_kernel<<<nB * LS_NG, LS_NT>>>(acids, mask, idx, out);
}